// round 6
// baseline (speedup 1.0000x reference)
#include <cuda_runtime.h>
#include <cuda_bf16.h>
#include <math.h>

// Problem constants
#define B_  8
#define C_  512
#define L_  1024
#define KN_ 4
#define KS_ 7
#define BCL (B_*C_*L_)          // 4194304
#define NTH 256
#define U_  4                   // L_/NTH elements per thread

// Bank-conflict-free swizzle for float2 smem FFT arrays (bank-pair = idx mod 16).
// Bijective (XORs constant into low4 per 16-aligned class); verified conflict-free
// for all radix-4 stage strides (1,4,16,64,256) and linear access.
#define SW(i) ((i) ^ (((i)>>4)&0xF) ^ (((i)>>2)&0xC))

// ---------------- device scratch (no allocations allowed) ----------------
__device__ float2 d_tw[L_];                 // forward twiddles W_1024^j
__device__ float  d_kern[KN_*KS_];
__device__ float  d_ssum[B_*L_];            // channel-sum of x
__device__ float2 d_vfs[B_*KN_*L_];         // FFT(x_shift)  (digit-reversed spectral domain)
__device__ float2 d_qf[B_*L_];              // FFT(q)        (digit-reversed spectral domain)
__device__ float2 d_vsum[B_*KN_];
__device__ float2 d_qsum[B_];
__device__ float2 d_means[2];               // mean_x, mean_y
__device__ float  d_weight[B_*KN_*L_];      // (digit-reversed spectral domain)
__device__ float2 d_P[B_*KN_*L_];           // qf*(1-w)      (digit-reversed spectral domain)
__device__ float  d_outputs[(size_t)B_*C_*KN_*L_];  // 64MB scratch
__device__ float  d_bnsum[64*L_];
__device__ float  d_bnsq[64*L_];
__device__ float  d_scale[L_];
__device__ float  d_shift[L_];

// ---------------- helpers ----------------
__device__ __forceinline__ float2 cmul(float2 a, float2 b) {
    return make_float2(a.x*b.x - a.y*b.y, a.x*b.y + a.y*b.x);
}

// Radix-4 DIF forward 1024-pt FFT, in place on swizzled shared array.
// Natural-order input, base-4 digit-reversed output.
__device__ __forceinline__ void fft1024_dif(float2* d, const float2* __restrict__ tw, int tid) {
#pragma unroll
    for (int stage = 0; stage < 5; ++stage) {
        const int qs = 8 - 2*stage;         // Q = 256 >> 2*stage
        const int Q  = 1 << qs;
        const int j   = tid & (Q - 1);
        const int blk = tid >> qs;
        const int base = (blk << (qs + 2)) + j;
        const int e = j << (8 - qs);        // twiddle W_{4Q}^{j*m} = tw[e*m mod 1024]

        float2 x0 = d[SW(base)];
        float2 x1 = d[SW(base + Q)];
        float2 x2 = d[SW(base + 2*Q)];
        float2 x3 = d[SW(base + 3*Q)];

        float2 t0 = make_float2(x0.x + x2.x, x0.y + x2.y);
        float2 t1 = make_float2(x0.x - x2.x, x0.y - x2.y);
        float2 t2 = make_float2(x1.x + x3.x, x1.y + x3.y);
        float2 t3 = make_float2(x1.x - x3.x, x1.y - x3.y);

        float2 y0 = make_float2(t0.x + t2.x, t0.y + t2.y);
        float2 u2 = make_float2(t0.x - t2.x, t0.y - t2.y);
        float2 u1 = make_float2(t1.x + t3.y, t1.y - t3.x);   // t1 - i*t3
        float2 u3 = make_float2(t1.x - t3.y, t1.y + t3.x);   // t1 + i*t3

        float2 w1 = tw[e];
        float2 w2 = tw[(2*e) & (L_-1)];
        float2 w3 = tw[(3*e) & (L_-1)];

        d[SW(base)]        = y0;
        d[SW(base + Q)]    = cmul(u1, w1);
        d[SW(base + 2*Q)]  = cmul(u2, w2);
        d[SW(base + 3*Q)]  = cmul(u3, w3);
        __syncthreads();
    }
}

// Radix-4 DIT inverse (unnormalized) 1024-pt FFT, in place on swizzled shared array.
// Base-4 digit-reversed input (= DIF output order), natural-order output.
__device__ __forceinline__ void fft1024_dit_inv(float2* d, const float2* __restrict__ tw, int tid) {
#pragma unroll
    for (int stage = 0; stage < 5; ++stage) {
        const int qs = 2*stage;
        const int Q  = 1 << qs;
        const int j   = tid & (Q - 1);
        const int blk = tid >> qs;
        const int base = (blk << (qs + 2)) + j;
        const int e = j * (256 >> qs);

        float2 x0 = d[SW(base)];
        float2 x1 = d[SW(base + Q)];
        float2 x2 = d[SW(base + 2*Q)];
        float2 x3 = d[SW(base + 3*Q)];

        float2 w1 = tw[e];
        float2 w2 = tw[(2*e) & (L_-1)];
        float2 w3 = tw[(3*e) & (L_-1)];
        w1.y = -w1.y; w2.y = -w2.y; w3.y = -w3.y;   // conjugate for inverse

        float2 a1 = cmul(x1, w1);
        float2 a2 = cmul(x2, w2);
        float2 a3 = cmul(x3, w3);

        float2 t0 = make_float2(x0.x + a2.x, x0.y + a2.y);
        float2 t1 = make_float2(x0.x - a2.x, x0.y - a2.y);
        float2 t2 = make_float2(a1.x + a3.x, a1.y + a3.y);
        float2 t3 = make_float2(a1.x - a3.x, a1.y - a3.y);

        float2 y0 = make_float2(t0.x + t2.x, t0.y + t2.y);
        float2 y2 = make_float2(t0.x - t2.x, t0.y - t2.y);
        float2 y1 = make_float2(t1.x - t3.y, t1.y + t3.x);   // t1 + i*t3 (inverse)
        float2 y3 = make_float2(t1.x + t3.y, t1.y - t3.x);   // t1 - i*t3 (inverse)

        d[SW(base)]       = y0;
        d[SW(base + Q)]   = y1;
        d[SW(base + 2*Q)] = y2;
        d[SW(base + 3*Q)] = y3;
        __syncthreads();
    }
}

// complex block-sum over 256 threads; valid on ALL threads on return
__device__ float2 blockReduceC(float2 v, float2* red) {
    __syncthreads();   // protect red[] from previous use
    for (int o = 16; o; o >>= 1) {
        v.x += __shfl_down_sync(0xffffffffu, v.x, o);
        v.y += __shfl_down_sync(0xffffffffu, v.y, o);
    }
    int warp = threadIdx.x >> 5, lane = threadIdx.x & 31;
    if (lane == 0) red[warp] = v;
    __syncthreads();
    if (threadIdx.x == 0) {
        float2 s = red[0];
        for (int w = 1; w < 8; ++w) { s.x += red[w].x; s.y += red[w].y; }
        red[0] = s;
    }
    __syncthreads();
    return red[0];
}

// float block-sum; result valid on thread 0 only
__device__ float blockReduceF(float v, float* red) {
    __syncthreads();
    for (int o = 16; o; o >>= 1) v += __shfl_down_sync(0xffffffffu, v, o);
    int warp = threadIdx.x >> 5, lane = threadIdx.x & 31;
    if (lane == 0) red[warp] = v;
    __syncthreads();
    float s = 0.f;
    if (threadIdx.x == 0) for (int w = 0; w < 8; ++w) s += red[w];
    return s;
}

// ---------------- kernel 0: twiddles + gaussian kernels ----------------
__global__ void setup_k(const float* __restrict__ sig, const float* __restrict__ cs) {
    int t = threadIdx.x;
    for (int j = t; j < L_; j += NTH) {
        double a = -2.0 * (double)j / (double)L_;
        double s, c; sincospi(a, &s, &c);
        d_tw[j] = make_float2((float)c, (float)s);
    }
    if (t < KN_) {
        float sg = sig[t] + 0.001f;
        float ctr = cs[t];
        float p[KS_]; float sum = 0.f;
#pragma unroll
        for (int j = 0; j < KS_; ++j) {
            float g = ((float)j - 3.0f - ctr) / sg;
            p[j] = expf(-0.5f * g * g);
            sum += p[j];
        }
        float inv = 1.0f / (sum + 0.01f);
#pragma unroll
        for (int j = 0; j < KS_; ++j) d_kern[t*KS_ + j] = p[j] * inv;
    }
}

// ---------------- kernel 1: channel sum + zero BN accumulators ----------------
__global__ void sumc_k(const float* __restrict__ x) {
    int bi = blockIdx.x, t = threadIdx.x;   // 32 blocks
    int b = bi >> 2;
    int l = (bi & 3) * NTH + t;
    float acc = 0.f;
    const float* p = x + (size_t)b * C_ * L_ + l;
    for (int c = 0; c < C_; ++c) acc += p[(size_t)c * L_];
    d_ssum[b*L_ + l] = acc;

    int g = bi * NTH + t;                   // zero 2*64*1024 floats
    for (int i = g; i < 64*L_; i += 32*NTH) { d_bnsum[i] = 0.f; d_bnsq[i] = 0.f; }
}

// ---------------- kernel 2: spectra (x_shift FFT + q FFT), DIF forward ----------------
__global__ __launch_bounds__(NTH) void spectra_k(const float* __restrict__ q) {
    __shared__ float2 work[L_];
    __shared__ float  sbuf[L_];
    __shared__ float2 red[8];
    int t = threadIdx.x, bi = blockIdx.x;   // 40 blocks

    if (bi < B_*KN_) {
        int b = bi >> 2, k = bi & 3;
        for (int i = t; i < L_; i += NTH) sbuf[i] = d_ssum[b*L_ + i];
        __syncthreads();
        for (int i = t; i < L_; i += NTH) {
            float acc = 0.f;
#pragma unroll
            for (int j = 0; j < KS_; ++j) {
                int idx = i - 3 + j;
                idx = idx < 0 ? 0 : (idx > L_-1 ? L_-1 : idx);
                acc += d_kern[k*KS_ + j] * sbuf[idx];
            }
            work[SW(i)] = make_float2(acc, 0.f);
        }
        __syncthreads();
        fft1024_dif(work, d_tw, t);
        float2 part = make_float2(0.f, 0.f);
        for (int i = t; i < L_; i += NTH) {
            float2 v = work[SW(i)];
            d_vfs[(size_t)bi*L_ + i] = v;     // digit-reversed spectral domain
            part.x += v.x; part.y += v.y;
        }
        part = blockReduceC(part, red);
        if (t == 0) d_vsum[bi] = part;
    } else {
        int b = bi - B_*KN_;
        for (int i = t; i < L_; i += NTH)
            work[SW(i)] = make_float2(q[b*L_ + i], 0.f);
        __syncthreads();
        fft1024_dif(work, d_tw, t);
        float2 part = make_float2(0.f, 0.f);
        for (int i = t; i < L_; i += NTH) {
            float2 v = work[SW(i)];
            d_qf[b*L_ + i] = v;               // digit-reversed spectral domain
            part.x += v.x; part.y += v.y;
        }
        part = blockReduceC(part, red);
        if (t == 0) d_qsum[b] = part;
    }
}

// ---------------- kernel 3: means ----------------
__global__ void means_k() {
    if (threadIdx.x == 0) {
        float2 s = make_float2(0.f, 0.f);
        for (int i = 0; i < B_*KN_; ++i) { s.x += d_vsum[i].x; s.y += d_vsum[i].y; }
        d_means[0] = make_float2(s.x / (float)(B_*KN_*L_), s.y / (float)(B_*KN_*L_));
        float2 s2 = make_float2(0.f, 0.f);
        for (int i = 0; i < B_; ++i) { s2.x += d_qsum[i].x; s2.y += d_qsum[i].y; }
        d_means[1] = make_float2(s2.x / (float)(B_*L_), s2.y / (float)(B_*L_));
    }
}

// ---------------- kernel 4: pearson weights (all in digit-reversed spectral domain) ----------------
__global__ __launch_bounds__(NTH) void weights_k() {
    __shared__ float2 xcb[L_];
    __shared__ float2 red[8];
    int t = threadIdx.x, bi = blockIdx.x;   // 32 blocks, bi = b*4+k
    int b = bi >> 2;
    float2 mx = d_means[0], my = d_means[1];

    float2 pa = make_float2(0.f, 0.f), pb = make_float2(0.f, 0.f);
    for (int i = t; i < L_; i += NTH) {
        float2 v  = d_vfs[(size_t)bi*L_ + i];
        float2 xc = make_float2(v.x - mx.x, v.y - mx.y);
        xcb[i] = xc;
        pa.x += xc.x*xc.x - xc.y*xc.y;
        pa.y += 2.f*xc.x*xc.y;
        float2 qv = d_qf[b*L_ + i];
        float2 qc = make_float2(qv.x - mx.x, qv.y - mx.y);  // reference bug kept: uses mean_x
        pb.x += qc.x*qc.x - qc.y*qc.y;
        pb.y += 2.f*qc.x*qc.y;
    }
    pa = blockReduceC(pa, red);
    pb = blockReduceC(pb, red);

    float2 den = cmul(pa, pb);
    den.x += 0.001f;
    float inv = 1.0f / (den.x*den.x + den.y*den.y);

    for (int i = t; i < L_; i += NTH) {
        float2 xc = xcb[i];
        float2 qv = d_qf[b*L_ + i];
        float2 yc = make_float2(qv.x - my.x, qv.y - my.y);
        float2 cov = cmul(xc, yc);
        float2 rho = make_float2((cov.x*den.x + cov.y*den.y) * inv,
                                 (cov.y*den.x - cov.x*den.y) * inv);
        float mag = sqrtf(rho.x*rho.x + rho.y*rho.y);
        float ang = atan2f(rho.y, rho.x + 0.0001f);
        float w = mag * tanhf(0.5f * ang);
        d_weight[(size_t)bi*L_ + i] = w;
        float om = 1.0f - w;
        d_P[(size_t)bi*L_ + i] = make_float2(qv.x*om, qv.y*om);
    }
}

// ---------------- kernel 5: main — per-(b,c) DIF FFT, 4 DIT iFFTs, outputs + BN partials ----------------
// 8KB smem/block (work only). x, X-spectrum, BN partials in registers:
// thread t privately owns the index set { t + u*256 : u<4 } for every
// elementwise phase, so no cross-thread hazards outside the FFTs themselves.
__global__ __launch_bounds__(NTH) void main_k(const float* __restrict__ x) {
    __shared__ float2 work[L_];
    int t = threadIdx.x, bi = blockIdx.x;   // 4096 blocks, bi = b*C + c
    int b = bi >> 9;

    float xr[U_], rs[U_], rq[U_];
    float2 Xr[U_];
    const float* xrow = x + (size_t)bi * L_;
#pragma unroll
    for (int u = 0; u < U_; ++u) {
        int i = t + u*NTH;
        float xv = xrow[i];
        xr[u] = xv; rs[u] = 0.f; rq[u] = 0.f;
        work[SW(i)] = make_float2(xv, 0.f);
    }
    __syncthreads();
    fft1024_dif(work, d_tw, t);      // ends with __syncthreads
#pragma unroll
    for (int u = 0; u < U_; ++u) Xr[u] = work[SW(t + u*NTH)];   // private reads

#pragma unroll
    for (int k = 0; k < KN_; ++k) {
        // mix-writes touch only this thread's private slots; previous readers of
        // those slots were this same thread — no sync needed here.
        size_t wb = ((size_t)b*KN_ + k) * L_;
#pragma unroll
        for (int u = 0; u < U_; ++u) {
            int i = t + u*NTH;
            float  w = d_weight[wb + i];
            float2 P = d_P[wb + i];
            work[SW(i)] = make_float2(P.x + Xr[u].x*w, P.y + Xr[u].y*w);
        }
        __syncthreads();             // publish mix before cross-thread FFT reads
        fft1024_dit_inv(work, d_tw, t);   // ends with __syncthreads
        size_t ob = ((size_t)bi*KN_ + k) * L_;
#pragma unroll
        for (int u = 0; u < U_; ++u) {
            int i = t + u*NTH;
            float2 v = work[SW(i)];  // private reads
            float val = sqrtf(v.x*v.x + v.y*v.y) * (1.0f / (float)L_) + xr[u];
            d_outputs[ob + i] = val;
            rs[u] += val;
            rq[u] += val * val;
        }
    }
    int bucket = bi & 63;
#pragma unroll
    for (int u = 0; u < U_; ++u) {
        int i = t + u*NTH;
        atomicAdd(&d_bnsum[bucket*L_ + i], rs[u]);
        atomicAdd(&d_bnsq [bucket*L_ + i], rq[u]);
    }
}

// ---------------- kernel 6: BN finalize ----------------
__global__ void bnfin_k(const float* __restrict__ gamma, const float* __restrict__ beta) {
    int l = blockIdx.x * NTH + threadIdx.x;   // grid 4
    if (l < L_) {
        float s = 0.f, sq = 0.f;
        for (int u = 0; u < 64; ++u) { s += d_bnsum[u*L_ + l]; sq += d_bnsq[u*L_ + l]; }
        const float invN = 1.0f / (float)(B_*C_*KN_);
        float mu  = s * invN;
        float var = sq * invN - mu*mu;
        float rs  = rsqrtf(var + 1e-5f);
        float sc  = rs * gamma[l];
        d_scale[l] = sc;
        d_shift[l] = beta[l] - mu * sc;
    }
}

// ---------------- kernel 7: attention (scores, softmax over KN, mix) ----------------
__global__ __launch_bounds__(NTH) void attn_k(const float* __restrict__ q, float* __restrict__ out) {
    __shared__ float red[8];
    __shared__ float wk4[KN_];
    int t = threadIdx.x, bi = blockIdx.x;   // 4096 blocks, bi = b*C + c
    int b = bi >> 9;

    float qr[U_], sclr[U_], shfr[U_], onr[KN_][U_];
#pragma unroll
    for (int u = 0; u < U_; ++u) {
        int i = t + u*NTH;
        qr[u]   = q[b*L_ + i];
        sclr[u] = d_scale[i];
        shfr[u] = d_shift[i];
    }

    float sc[KN_];
    size_t ob = (size_t)bi * KN_ * L_;
#pragma unroll
    for (int k = 0; k < KN_; ++k) {
        float p = 0.f;
#pragma unroll
        for (int u = 0; u < U_; ++u) {
            int i = t + u*NTH;
            float on = d_outputs[ob + (size_t)k*L_ + i] * sclr[u] + shfr[u];
            onr[k][u] = on;
            p += qr[u] * on;
        }
        sc[k] = blockReduceF(p, red);   // valid on thread 0
    }
    if (t == 0) {
        float m = fmaxf(fmaxf(sc[0], sc[1]), fmaxf(sc[2], sc[3]));
        float e0 = expf(sc[0]-m), e1 = expf(sc[1]-m), e2 = expf(sc[2]-m), e3 = expf(sc[3]-m);
        float inv = 1.0f / (e0 + e1 + e2 + e3);
        wk4[0] = e0*inv; wk4[1] = e1*inv; wk4[2] = e2*inv; wk4[3] = e3*inv;
    }
    __syncthreads();
    float w0 = wk4[0], w1 = wk4[1], w2 = wk4[2], w3 = wk4[3];
#pragma unroll
    for (int u = 0; u < U_; ++u) {
        int i = t + u*NTH;
        out[(size_t)bi*L_ + i] = w0*onr[0][u] + w1*onr[1][u] + w2*onr[2][u] + w3*onr[3][u];
    }
}

// ---------------- kernel 8: zero tail (tuple scalar output) ----------------
__global__ void tail_k(float* out, int out_size) {
    int i = BCL + blockIdx.x * NTH + threadIdx.x;
    if (i < out_size) out[i] = 0.f;
}

// ---------------- launch ----------------
extern "C" void kernel_launch(void* const* d_in, const int* in_sizes, int n_in,
                              void* d_out, int out_size) {
    const float* x     = (const float*)d_in[0];
    const float* q     = (const float*)d_in[1];
    const float* sig   = (const float*)d_in[2];
    const float* cs    = (const float*)d_in[3];
    const float* gamma = (const float*)d_in[4];
    const float* beta  = (const float*)d_in[5];
    float* out = (float*)d_out;

    setup_k  <<<1, NTH>>>(sig, cs);
    sumc_k   <<<32, NTH>>>(x);
    spectra_k<<<B_*KN_ + B_, NTH>>>(q);
    means_k  <<<1, 32>>>();
    weights_k<<<B_*KN_, NTH>>>();
    main_k   <<<B_*C_, NTH>>>(x);
    bnfin_k  <<<(L_ + NTH - 1) / NTH, NTH>>>(gamma, beta);
    attn_k   <<<B_*C_, NTH>>>(q, out);

    int tail = out_size - BCL;
    if (tail > 0) tail_k<<<(tail + NTH - 1) / NTH, NTH>>>(out, out_size);
}